// round 6
// baseline (speedup 1.0000x reference)
#include <cuda_runtime.h>

#define N_PRED 20
#define N_LAB  12
#define HALF   10
#define ROWS   128           // rows per CTA (256 threads, 2 per row)
#define LPAD   132           // padded row length for label SoA (bank-conflict-free)

__device__ __forceinline__ float sqrt_approx(float x){ float r; asm("sqrt.approx.f32 %0,%1;":"=f"(r):"f"(x)); return r; }
__device__ __forceinline__ float log2_approx(float x){ float r; asm("lg2.approx.f32 %0,%1;":"=f"(r):"f"(x)); return r; }

__global__ __launch_bounds__(256, 4)
void myloss_kernel(const float4* __restrict__ pred,   // [B, 20, 4]
                   const float4* __restrict__ label,  // [B, 12, 4]
                   float* __restrict__ out, int B)
{
    __shared__ float lx[N_LAB * LPAD];
    __shared__ float ly[N_LAB * LPAD];
    __shared__ float lz[N_LAB * LPAD];

    int tid = threadIdx.x;
    int r0  = blockIdx.x * ROWS;              // first row of this CTA
    int p   = tid >> 1;                       // local row (pair) index 0..127
    int h   = tid & 1;                        // which half of the preds
    int b   = r0 + p;
    bool valid = (b < B);
    int bc = valid ? b : (B - 1);             // clamped row for safe global reads

    // ---- my 10 preds -> registers (front-batched LDG.128, overlaps staging) ----
    float px[HALF], py[HALF], pz[HALF], pw[HALF];
    const float4* pr = pred + (long)bc * N_PRED + h * HALF;
    #pragma unroll
    for (int j = 0; j < HALF; j++) {
        float4 v = pr[j];
        px[j] = v.x; py[j] = v.y; pz[j] = v.z; pw[j] = v.w;
    }

    // ---- cooperative label staging: contiguous 24KB -> SoA smem ----
    {
        int n_rows = min(ROWS, B - r0);
        int n4 = n_rows * N_LAB;              // float4 count
        const float4* base = label + (long)r0 * N_LAB;
        for (int i = tid; i < n4; i += 256) { // fully coalesced global reads
            float4 v = base[i];
            int row = i / N_LAB, l = i - row * N_LAB;
            lx[l * LPAD + row] = v.x;
            ly[l * LPAD + row] = v.y;
            lz[l * LPAD + row] = v.z;         // w unused
        }
    }
    __syncthreads();

    float csum = 0.f;                  // sum of winning scaled costs (dist+rdiff)
    unsigned long long cnt = 0ull;     // 4-bit match multiplicity per local pred
    const int gbase = HALF * h;        // my first global pred index

    #pragma unroll
    for (int l = 0; l < N_LAB; l++) {
        float yx = lx[l * LPAD + p];   // broadcast within thread pair, no conflicts
        float yy = ly[l * LPAD + p];
        float yz = lz[l * LPAD + p];

        // Keys: low 5 mantissa bits carry the global pred index, so nonneg
        // float min == lexicographic (cost, idx) min == jnp.argmin tie-break.
        float m[5];
        #pragma unroll
        for (int q = 0; q < 5; q++) {
            int j0 = 2*q, j1 = 2*q + 1;
            float dx0 = yx - px[j0], dy0 = yy - py[j0];
            float c0  = sqrt_approx(fmaf(dx0, dx0, dy0*dy0)) + fabsf(yz - pz[j0]);
            float dx1 = yx - px[j1], dy1 = yy - py[j1];
            float c1  = sqrt_approx(fmaf(dx1, dx1, dy1*dy1)) + fabsf(yz - pz[j1]);
            float k0 = __uint_as_float((__float_as_uint(c0) & 0xFFFFFFE0u) | (unsigned)(gbase + j0));
            float k1 = __uint_as_float((__float_as_uint(c1) & 0xFFFFFFE0u) | (unsigned)(gbase + j1));
            m[q] = fminf(k0, k1);
        }
        float w = fminf(fminf(fminf(m[0], m[1]), fminf(m[2], m[3])), m[4]);

        // Cross-thread merge (keys unique -> bitwise ownership test).
        float o  = __shfl_xor_sync(0xffffffffu, w, 1);
        float wc = fminf(w, o);
        csum += __uint_as_float(__float_as_uint(wc) & 0xFFFFFFE0u);  // strip idx noise
        if (__float_as_uint(wc) == __float_as_uint(w)) {
            int loc = (int)(__float_as_uint(w) & 31u) - gbase;       // 0..9
            cnt += 1ull << (4 * loc);
        }
    }

    // ---- epilogue: exactly one log per pred ----
    //   matched (n>0): -n*log(pw+eps)/12
    //   unmatched:     (-log(1-pw+eps) + 0.5*pz)*0.5/8
    const float EPS = 1e-6f;
    const float LN2 = 0.69314718055994530942f;
    float S = 0.f;
    #pragma unroll
    for (int j = 0; j < HALF; j++) {
        int n = (int)((cnt >> (4*j)) & 15ull);
        bool mt = (n > 0);
        float arg  = mt ? (pw[j] + EPS) : ((1.0f + EPS) - pw[j]);
        float lg   = log2_approx(arg);
        float coef = mt ? ((float)n) * (-LN2 / 12.0f) : (-LN2 / 16.0f);
        S = fmaf(coef, lg, S);
        if (!mt) S = fmaf(pz[j], 1.0f / 32.0f, S);
    }
    S += __shfl_xor_sync(0xffffffffu, S, 1);          // partner half

    if (valid && h == 0)
        out[b] = fmaf(csum, 0.5f / 12.0f, S);
}

extern "C" void kernel_launch(void* const* d_in, const int* in_sizes, int n_in,
                              void* d_out, int out_size)
{
    const float4* pred  = (const float4*)d_in[0];
    const float4* label = (const float4*)d_in[1];
    float* out = (float*)d_out;
    int B = in_sizes[0] / (N_PRED * 4);

    int blocks = (B + ROWS - 1) / ROWS;
    myloss_kernel<<<blocks, 256>>>(pred, label, out, B);
}

// round 7
// speedup vs baseline: 1.2652x; 1.2652x over previous
#include <cuda_runtime.h>

#define N_PRED 20
#define N_LAB  12
#define QTR    5     // preds per thread (4 threads per row)

__device__ __forceinline__ float sqrt_approx(float x){ float r; asm("sqrt.approx.f32 %0,%1;":"=f"(r):"f"(x)); return r; }
__device__ __forceinline__ float log2_approx(float x){ float r; asm("lg2.approx.f32 %0,%1;":"=f"(r):"f"(x)); return r; }

__global__ __launch_bounds__(256, 5)
void myloss_kernel(const float4* __restrict__ pred,   // [B, 20, 4]
                   const float4* __restrict__ label,  // [B, 12, 4]
                   float* __restrict__ out, int B)
{
    int t = blockIdx.x * blockDim.x + threadIdx.x;
    int b = t >> 2;          // row
    int h = t & 3;           // quarter of the preds owned by this thread
    bool valid = (b < B);
    if (!valid) b = B - 1;   // keep warps converged for the shuffles

    // My 5 preds in registers (contiguous 80B -> coalesced float4 loads).
    float px[QTR], py[QTR], pz[QTR], pw[QTR];
    const float4* pr = pred + (long)b * N_PRED + h * QTR;
    #pragma unroll
    for (int j = 0; j < QTR; j++) {
        float4 v = pr[j];
        px[j] = v.x; py[j] = v.y; pz[j] = v.z; pw[j] = v.w;
    }

    const float4* lb = label + (long)b * N_LAB;
    float csum = 0.f;          // sum of winning scaled costs (dist + rdiff)
    unsigned cnt = 0u;         // 4-bit match multiplicity per local pred (5 nibbles)
    const int gbase = QTR * h; // my first global pred index

    #pragma unroll
    for (int l = 0; l < N_LAB; l++) {
        float4 y = lb[l];      // 4 lanes share the sector -> L1 broadcast

        // Keys: low 5 mantissa bits carry the GLOBAL pred index, so a plain
        // nonneg-float min is an exact lexicographic (cost, idx) min
        // == jnp.argmin first-min tie-break across all 20 preds.
        float m[QTR];
        #pragma unroll
        for (int j = 0; j < QTR; j++) {
            float dx = y.x - px[j], dy = y.y - py[j];
            float c  = sqrt_approx(fmaf(dx, dx, dy * dy)) + fabsf(y.z - pz[j]);
            m[j] = __uint_as_float((__float_as_uint(c) & 0xFFFFFFE0u) | (unsigned)(gbase + j));
        }
        float w  = fminf(fminf(fminf(m[0], m[1]), fminf(m[2], m[3])), m[4]);

        // 2-round merge across the 4 lanes of this row.
        float w1 = fminf(w,  __shfl_xor_sync(0xffffffffu, w,  1));
        float wc = fminf(w1, __shfl_xor_sync(0xffffffffu, w1, 2));

        csum += __uint_as_float(__float_as_uint(wc) & 0xFFFFFFE0u); // strip idx bits
        if (__float_as_uint(wc) == __float_as_uint(w)) {            // unique keys:
            int j = (int)(__float_as_uint(w) & 31u) - gbase;        // exactly one lane
            cnt += 1u << (4 * j);
        }
    }

    // Epilogue: exactly one log per pred.
    //   matched (n>0): -n*log(pw+eps)/12
    //   unmatched:     (-log(1-pw+eps) + 0.5*pz)*0.5/8
    const float EPS = 1e-6f;
    const float LN2 = 0.69314718055994530942f;
    float S = 0.f;
    #pragma unroll
    for (int j = 0; j < QTR; j++) {
        int n = (int)((cnt >> (4 * j)) & 15u);
        bool mt = (n > 0);
        float arg  = mt ? (pw[j] + EPS) : ((1.0f + EPS) - pw[j]);
        float lg   = log2_approx(arg);
        float coef = mt ? ((float)n) * (-LN2 / 12.0f) : (-LN2 / 16.0f);
        S = fmaf(coef, lg, S);
        if (!mt) S = fmaf(pz[j], 1.0f / 32.0f, S);
    }
    S += __shfl_xor_sync(0xffffffffu, S, 1);
    S += __shfl_xor_sync(0xffffffffu, S, 2);

    if (valid && h == 0)
        out[b] = fmaf(csum, 0.5f / 12.0f, S);
}

extern "C" void kernel_launch(void* const* d_in, const int* in_sizes, int n_in,
                              void* d_out, int out_size)
{
    const float4* pred  = (const float4*)d_in[0];
    const float4* label = (const float4*)d_in[1];
    float* out = (float*)d_out;
    int B = in_sizes[0] / (N_PRED * 4);

    long threads_total = 4L * B;
    int threads = 256;
    int blocks = (int)((threads_total + threads - 1) / threads);
    myloss_kernel<<<blocks, threads>>>(pred, label, out, B);
}